// round 1
// baseline (speedup 1.0000x reference)
#include <cuda_runtime.h>
#include <cuda_bf16.h>
#include <math.h>

// ---------------- problem constants ----------------
#define BB 32
#define KK 2048
#define CC 256
#define PP 256
#define SS 16
#define NCOL (BB*PP*SS)      // 131072
#define NP   (BB*PP)         // 8192
#define KP1  272             // 259 padded to mult of 16
#define OUTC 119

// output section offsets (floats)
#define OFF_OBJ      0
#define OFF_CENTER   16384
#define OFF_SS       40960
#define OFF_SRES     188416
#define OFF_PSIZE    630784
#define OFF_SEM      655360
#define OFF_CORN     802816
#define OFF_SLOG     999424
#define OFF_OPROB    1155072
#define OFF_SPROB    1163264

// ---------------- scratch (device globals; zero-init guaranteed) ----------------
__device__ float g_X1[KP1 * NCOL];     // gathered input, rows 259..271 stay 0
__device__ float g_A1[CC * NCOL];
__device__ float g_A2[CC * NCOL];
__device__ float g_Y [CC * NP];
__device__ float g_Y2[CC * NP];
__device__ float g_Y3[CC * NP];
__device__ float g_NET[OUTC * NP];
__device__ float g_NX[NP * 3];         // new_xyz
__device__ int   g_IDX[NP * SS];       // ball query indices
__device__ float g_W1P[CC * KP1];      // padded sa_w1

// ---------------- helpers ----------------
__device__ __forceinline__ float d2_nofma(float ax,float ay,float az,float bx,float by,float bz){
    float dx=ax-bx, dy=ay-by, dz=az-bz;
    return __fadd_rn(__fadd_rn(__fmul_rn(dx,dx),__fmul_rn(dy,dy)),__fmul_rn(dz,dz));
}

// ---------------- FPS: one block per batch ----------------
__global__ __launch_bounds__(1024) void fps_kernel(const float* __restrict__ xyz)
{
    __shared__ float sx[KK], sy[KK], sz[KK];
    __shared__ float rv[32]; __shared__ int ri[32]; __shared__ int sfar;
    const int b = blockIdx.x, tid = threadIdx.x;
    const float* xb = xyz + (size_t)b*KK*3;
    for (int i=tid;i<KK;i+=1024){ sx[i]=xb[i*3+0]; sy[i]=xb[i*3+1]; sz[i]=xb[i*3+2]; }
    __syncthreads();
    const int i0 = tid, i1 = tid + 1024;
    float d0 = 1e10f, d1 = 1e10f;
    int far = 0;
    const float x0=sx[i0], y0=sy[i0], z0=sz[i0];
    const float x1=sx[i1], y1=sy[i1], z1=sz[i1];
    for (int it=0; it<PP; ++it){
        if (tid==0){
            g_NX[(b*PP+it)*3+0]=sx[far];
            g_NX[(b*PP+it)*3+1]=sy[far];
            g_NX[(b*PP+it)*3+2]=sz[far];
        }
        const float cx=sx[far], cy=sy[far], cz=sz[far];
        d0 = fminf(d0, d2_nofma(x0,y0,z0,cx,cy,cz));
        d1 = fminf(d1, d2_nofma(x1,y1,z1,cx,cy,cz));
        float bv = d0; int bi = i0;
        if (d1 > bv){ bv=d1; bi=i1; }
        #pragma unroll
        for (int off=16; off; off>>=1){
            float ov=__shfl_down_sync(0xffffffffu,bv,off);
            int   oi=__shfl_down_sync(0xffffffffu,bi,off);
            if (ov>bv || (ov==bv && oi<bi)){ bv=ov; bi=oi; }
        }
        const int w = tid>>5, lane = tid&31;
        if (lane==0){ rv[w]=bv; ri[w]=bi; }
        __syncthreads();
        if (w==0){
            bv = rv[lane]; bi = ri[lane];
            #pragma unroll
            for (int off=16; off; off>>=1){
                float ov=__shfl_down_sync(0xffffffffu,bv,off);
                int   oi=__shfl_down_sync(0xffffffffu,bi,off);
                if (ov>bv || (ov==bv && oi<bi)){ bv=ov; bi=oi; }
            }
            if (lane==0) sfar = bi;
        }
        __syncthreads();
        far = sfar;
    }
}

// ---------------- ball query: one warp per proposal, xyz in smem ----------------
__global__ __launch_bounds__(256) void ballq_kernel(const float* __restrict__ xyz)
{
    __shared__ float sx[KK], sy[KK], sz[KK];
    const int b = blockIdx.x >> 5;           // 32 blocks per batch
    const float* xb = xyz + (size_t)b*KK*3;
    for (int i=threadIdx.x;i<KK;i+=256){ sx[i]=xb[i*3+0]; sy[i]=xb[i*3+1]; sz[i]=xb[i*3+2]; }
    __syncthreads();
    const int warp = threadIdx.x>>5, lane = threadIdx.x&31;
    const int w = blockIdx.x*8 + warp;       // global proposal id = b*PP + p
    const float cx=g_NX[w*3+0], cy=g_NX[w*3+1], cz=g_NX[w*3+2];
    int cnt=0, firstIdx=0; bool haveFirst=false;
    for (int j=0;j<KK;j+=32){
        const int i = j + lane;
        const float dd = d2_nofma(sx[i],sy[i],sz[i],cx,cy,cz);
        const bool within = dd < 0.09f;
        const unsigned mask = __ballot_sync(0xffffffffu, within);
        if (mask){
            if (!haveFirst){ firstIdx = j + __ffs(mask) - 1; haveFirst=true; }
            const int rank = __popc(mask & ((1u<<lane)-1u));
            if (within && (cnt+rank) < SS) g_IDX[w*SS + cnt + rank] = i;
            cnt += __popc(mask);
            if (cnt >= SS) break;
        }
    }
    if (cnt < SS && lane >= cnt && lane < SS) g_IDX[w*SS + lane] = firstIdx;
}

// ---------------- pad sa_w1 -> [256][272] ----------------
__global__ void prep_w1(const float* __restrict__ w1)
{
    int t = blockIdx.x*256 + threadIdx.x;
    if (t < CC*KP1){
        int m = t / KP1, k = t % KP1;
        g_W1P[t] = (k < 259) ? w1[m*259 + k] : 0.0f;
    }
}

// ---------------- gather xyz channels into X1 rows 0..2 ----------------
__global__ void gatherx_kernel(const float* __restrict__ xyz)
{
    int t = blockIdx.x*256 + threadIdx.x;     // < NCOL
    int b = t >> 12;                           // /4096
    int p = (t >> 4) & 255;
    int i = g_IDX[t];
    const float* xb = xyz + (size_t)b*KK*3 + (size_t)i*3;
    const float* nc = g_NX + (b*PP + p)*3;
    g_X1[0*NCOL + t] = (xb[0]-nc[0]) / 0.3f;
    g_X1[1*NCOL + t] = (xb[1]-nc[1]) / 0.3f;
    g_X1[2*NCOL + t] = (xb[2]-nc[2]) / 0.3f;
}

// ---------------- gather features into X1 rows 3..258 ----------------
__global__ __launch_bounds__(256) void gatherf_kernel(const float* __restrict__ features)
{
    __shared__ float row[KK];
    const int c = blockIdx.x, b = blockIdx.y;
    const float* src = features + ((size_t)b*CC + c)*KK;
    for (int i=threadIdx.x;i<KK;i+=256) row[i]=src[i];
    __syncthreads();
    float* dst = g_X1 + (size_t)(3+c)*NCOL + b*(PP*SS);
    const int* ib = g_IDX + b*(PP*SS);
    #pragma unroll
    for (int it=0; it<16; ++it){
        int cl = it*256 + threadIdx.x;
        dst[cl] = row[ib[cl]];
    }
}

// ---------------- tiled SGEMM with fused BN/bias + ReLU epilogue ----------------
// Out[M,N] = act( (W[M,Kc] @ X[Kc,N]) * s + sh )
#define BMt 64
#define BNt 64
#define BKt 16
__global__ __launch_bounds__(256) void gemm_kernel(
    const float* __restrict__ W, const float* __restrict__ X, float* __restrict__ Out,
    int M, int Kc, int N,
    const float* __restrict__ gamma, const float* __restrict__ beta,
    const float* __restrict__ mean,  const float* __restrict__ var,
    const float* __restrict__ bias, int do_relu)
{
    __shared__ float Ws[BKt][BMt+4];
    __shared__ float Xs[BKt][BNt+4];
    const int tid = threadIdx.x;
    const int tx = tid & 15, ty = tid >> 4;
    const int row0 = blockIdx.y*BMt, col0 = blockIdx.x*BNt;
    float acc[4][4] = {};
    const int wm = tid >> 2;                // 0..63
    const int wk = (tid & 3) * 4;           // 0,4,8,12
    const int xk = tid >> 4;                // 0..15
    const int xn = (tid & 15) * 4;          // 0..60

    for (int kt=0; kt<Kc; kt+=BKt){
        float4 wv = make_float4(0.f,0.f,0.f,0.f);
        const int gm = row0 + wm;
        if (gm < M) wv = *reinterpret_cast<const float4*>(&W[(size_t)gm*Kc + kt + wk]);
        Ws[wk+0][wm]=wv.x; Ws[wk+1][wm]=wv.y; Ws[wk+2][wm]=wv.z; Ws[wk+3][wm]=wv.w;
        float4 xv = *reinterpret_cast<const float4*>(&X[(size_t)(kt+xk)*N + col0 + xn]);
        *reinterpret_cast<float4*>(&Xs[xk][xn]) = xv;
        __syncthreads();
        #pragma unroll
        for (int k=0;k<BKt;k++){
            float a0=Ws[k][ty*4+0], a1=Ws[k][ty*4+1], a2=Ws[k][ty*4+2], a3=Ws[k][ty*4+3];
            float b0=Xs[k][tx*4+0], b1=Xs[k][tx*4+1], b2=Xs[k][tx*4+2], b3=Xs[k][tx*4+3];
            acc[0][0]+=a0*b0; acc[0][1]+=a0*b1; acc[0][2]+=a0*b2; acc[0][3]+=a0*b3;
            acc[1][0]+=a1*b0; acc[1][1]+=a1*b1; acc[1][2]+=a1*b2; acc[1][3]+=a1*b3;
            acc[2][0]+=a2*b0; acc[2][1]+=a2*b1; acc[2][2]+=a2*b2; acc[2][3]+=a2*b3;
            acc[3][0]+=a3*b0; acc[3][1]+=a3*b1; acc[3][2]+=a3*b2; acc[3][3]+=a3*b3;
        }
        __syncthreads();
    }
    #pragma unroll
    for (int i=0;i<4;i++){
        const int m = row0 + ty*4 + i;
        if (m >= M) continue;
        float s = 1.f, sh = 0.f;
        if (gamma){
            const float sc = gamma[m] * rsqrtf(var[m] + 1e-5f);
            s = sc; sh = beta[m] - mean[m]*sc;
        } else if (bias){
            sh = bias[m];
        }
        float4 o;
        o.x = acc[i][0]*s + sh; o.y = acc[i][1]*s + sh;
        o.z = acc[i][2]*s + sh; o.w = acc[i][3]*s + sh;
        if (do_relu){
            o.x=fmaxf(o.x,0.f); o.y=fmaxf(o.y,0.f); o.z=fmaxf(o.z,0.f); o.w=fmaxf(o.w,0.f);
        }
        *reinterpret_cast<float4*>(&Out[(size_t)m*N + col0 + tx*4]) = o;
    }
}

// ---------------- max over samples: A1[oc][(bp)*16+s] -> Y[oc][bp] ----------------
__global__ void maxpool_kernel()
{
    int id = blockIdx.x*256 + threadIdx.x;   // < CC*NP
    int oc = id >> 13, cp = id & (NP-1);
    const float4* p = reinterpret_cast<const float4*>(g_A1 + (size_t)oc*NCOL + cp*SS);
    float4 a=p[0], b=p[1], c=p[2], d=p[3];
    float m = fmaxf(fmaxf(fmaxf(a.x,a.y),fmaxf(a.z,a.w)),
               fmaxf(fmaxf(fmaxf(b.x,b.y),fmaxf(b.z,b.w)),
               fmaxf(fmaxf(fmaxf(c.x,c.y),fmaxf(c.z,c.w)),
                     fmaxf(fmaxf(d.x,d.y),fmaxf(d.z,d.w)))));
    g_Y[(size_t)oc*NP + cp] = m;
}

// ---------------- head: everything after p_w3 ----------------
__global__ __launch_bounds__(256) void head_kernel(const float* __restrict__ msa,
                                                   float* __restrict__ out)
{
    const int t = blockIdx.x*256 + threadIdx.x;   // < NP
    #define NT(j) g_NET[(j)*NP + t]
    const float obj0 = NT(0), obj1 = NT(1);
    out[OFF_OBJ + t*2 + 0] = obj0;
    out[OFF_OBJ + t*2 + 1] = obj1;
    const float c0 = g_NX[t*3+0] + NT(2);
    const float c1 = g_NX[t*3+1] + NT(3);
    const float c2 = g_NX[t*3+2] + NT(4);
    out[OFF_CENTER + t*3 + 0] = c0;
    out[OFF_CENTER + t*3 + 1] = c1;
    out[OFF_CENTER + t*3 + 2] = c2;

    float ss[18];
    #pragma unroll
    for (int k=0;k<18;k++){ ss[k] = NT(29+k); out[OFF_SS + t*18 + k] = ss[k]; }
    int best = 0; float bv = ss[0];
    #pragma unroll
    for (int k=1;k<18;k++) if (ss[k] > bv){ bv = ss[k]; best = k; }

    float ps0=0.f, ps1=0.f, ps2=0.f;
    #pragma unroll
    for (int k=0;k<18;k++){
        const float m0=msa[k*3+0], m1=msa[k*3+1], m2=msa[k*3+2];
        const float r0 = NT(47+k*3+0)*m0;
        const float r1 = NT(47+k*3+1)*m1;
        const float r2 = NT(47+k*3+2)*m2;
        out[OFF_SRES + t*54 + k*3 + 0] = r0;
        out[OFF_SRES + t*54 + k*3 + 1] = r1;
        out[OFF_SRES + t*54 + k*3 + 2] = r2;
        if (k == best){ ps0 = r0+m0; ps1 = r1+m1; ps2 = r2+m2; }
    }
    out[OFF_PSIZE + t*3 + 0] = ps0;
    out[OFF_PSIZE + t*3 + 1] = ps1;
    out[OFF_PSIZE + t*3 + 2] = ps2;

    float sm[18];
    #pragma unroll
    for (int k=0;k<18;k++){ sm[k] = NT(101+k); out[OFF_SEM + t*18 + k] = sm[k]; }

    // corners (angle = 0 -> R = identity)
    const float cc0 = c0, cc1 = c2, cc2 = -c1;
    const float hx = ps0*0.5f, hy = ps2*0.5f, hz = ps1*0.5f;
    const float SX[8]={1,1,-1,-1,1,1,-1,-1};
    const float SY[8]={1,1,1,1,-1,-1,-1,-1};
    const float SZ[8]={1,-1,-1,1,1,-1,-1,1};
    #pragma unroll
    for (int i=0;i<8;i++){
        out[OFF_CORN + t*24 + i*3 + 0] = cc0 + hx*SX[i];
        out[OFF_CORN + t*24 + i*3 + 1] = cc1 + hy*SY[i];
        out[OFF_CORN + t*24 + i*3 + 2] = cc2 + hz*SZ[i];
    }

    // sem_logits
    #pragma unroll
    for (int k=0;k<18;k++) out[OFF_SLOG + t*19 + k] = sm[k];
    out[OFF_SLOG + t*19 + 18] = (obj0 <= obj1) ? 0.0f : 1e10f;

    // obj_prob = softmax(obj)[1]
    {
        const float mx = fmaxf(obj0,obj1);
        const float e0 = expf(obj0-mx), e1 = expf(obj1-mx);
        out[OFF_OPROB + t] = e1/(e0+e1);
    }
    // sem_prob = softmax(sem)
    {
        float mx = sm[0];
        #pragma unroll
        for (int k=1;k<18;k++) mx = fmaxf(mx, sm[k]);
        float e[18], ssum = 0.f;
        #pragma unroll
        for (int k=0;k<18;k++){ e[k] = expf(sm[k]-mx); ssum += e[k]; }
        #pragma unroll
        for (int k=0;k<18;k++) out[OFF_SPROB + t*18 + k] = e[k]/ssum;
    }
    #undef NT
}

// ---------------- host launcher ----------------
extern "C" void kernel_launch(void* const* d_in, const int* in_sizes, int n_in,
                              void* d_out, int out_size)
{
    const float* xyz      = (const float*)d_in[0];
    const float* features = (const float*)d_in[1];
    const float* sa_w1    = (const float*)d_in[2];
    const float* sa_w2    = (const float*)d_in[3];
    const float* sa_w3    = (const float*)d_in[4];
    const float* sa_gamma = (const float*)d_in[5];
    const float* sa_beta  = (const float*)d_in[6];
    const float* sa_mean  = (const float*)d_in[7];
    const float* sa_var   = (const float*)d_in[8];
    const float* p_w1     = (const float*)d_in[9];
    const float* p_w2     = (const float*)d_in[10];
    const float* p_w3     = (const float*)d_in[11];
    const float* p_b3     = (const float*)d_in[12];
    const float* p_gamma  = (const float*)d_in[13];
    const float* p_beta   = (const float*)d_in[14];
    const float* p_mean   = (const float*)d_in[15];
    const float* p_var    = (const float*)d_in[16];
    const float* msa      = (const float*)d_in[17];
    float* out = (float*)d_out;

    void *pX1, *pA1, *pA2, *pY, *pY2, *pY3, *pNET, *pW1P;
    cudaGetSymbolAddress(&pX1, g_X1);
    cudaGetSymbolAddress(&pA1, g_A1);
    cudaGetSymbolAddress(&pA2, g_A2);
    cudaGetSymbolAddress(&pY,  g_Y);
    cudaGetSymbolAddress(&pY2, g_Y2);
    cudaGetSymbolAddress(&pY3, g_Y3);
    cudaGetSymbolAddress(&pNET, g_NET);
    cudaGetSymbolAddress(&pW1P, g_W1P);

    fps_kernel<<<BB, 1024>>>(xyz);
    ballq_kernel<<<1024, 256>>>(xyz);
    prep_w1<<<(CC*KP1 + 255)/256, 256>>>(sa_w1);
    gatherx_kernel<<<NCOL/256, 256>>>(xyz);
    gatherf_kernel<<<dim3(CC, BB), 256>>>(features);

    // SA conv stack
    gemm_kernel<<<dim3(NCOL/BNt, CC/BMt), 256>>>((const float*)pW1P, (const float*)pX1, (float*)pA1,
        CC, KP1, NCOL, sa_gamma+0, sa_beta+0, sa_mean+0, sa_var+0, nullptr, 1);
    gemm_kernel<<<dim3(NCOL/BNt, CC/BMt), 256>>>(sa_w2, (const float*)pA1, (float*)pA2,
        CC, CC, NCOL, sa_gamma+256, sa_beta+256, sa_mean+256, sa_var+256, nullptr, 1);
    gemm_kernel<<<dim3(NCOL/BNt, CC/BMt), 256>>>(sa_w3, (const float*)pA2, (float*)pA1,
        CC, CC, NCOL, sa_gamma+512, sa_beta+512, sa_mean+512, sa_var+512, nullptr, 1);

    maxpool_kernel<<<(CC*NP)/256, 256>>>();

    // proposal FCs
    gemm_kernel<<<dim3(NP/BNt, CC/BMt), 256>>>(p_w1, (const float*)pY, (float*)pY2,
        CC, CC, NP, p_gamma+0, p_beta+0, p_mean+0, p_var+0, nullptr, 1);
    gemm_kernel<<<dim3(NP/BNt, CC/BMt), 256>>>(p_w2, (const float*)pY2, (float*)pY3,
        CC, CC, NP, p_gamma+256, p_beta+256, p_mean+256, p_var+256, nullptr, 1);
    gemm_kernel<<<dim3(NP/BNt, (OUTC+BMt-1)/BMt), 256>>>(p_w3, (const float*)pY3, (float*)pNET,
        OUTC, CC, NP, nullptr, nullptr, nullptr, nullptr, p_b3, 0);

    head_kernel<<<NP/256, 256>>>(msa, out);
}

// round 3
// speedup vs baseline: 1.2088x; 1.2088x over previous
#include <cuda_runtime.h>
#include <cuda_bf16.h>
#include <math.h>
#include <cstdint>

// ---------------- problem constants ----------------
#define BB 32
#define KK 2048
#define CC 256
#define PP 256
#define SS 16
#define NCOL (BB*PP*SS)      // 131072
#define NP   (BB*PP)         // 8192
#define KP   320             // 259 padded to mult of 32
#define OUTC 119

// output section offsets (floats)
#define OFF_OBJ      0
#define OFF_CENTER   16384
#define OFF_SS       40960
#define OFF_SRES     188416
#define OFF_PSIZE    630784
#define OFF_SEM      655360
#define OFF_CORN     802816
#define OFF_SLOG     999424
#define OFF_OPROB    1155072
#define OFF_SPROB    1163264

// ---------------- scratch (device globals; zero-init guaranteed) ----------------
__device__ __nv_bfloat16 g_X1a[(size_t)KP * NCOL];   // plane 1 (rows 259..319 stay 0)
__device__ __nv_bfloat16 g_X1b[(size_t)KP * NCOL];   // plane 2
__device__ __nv_bfloat16 g_X1c[(size_t)KP * NCOL];   // plane 3
__device__ __nv_bfloat16 g_A1a[(size_t)CC * NCOL];
__device__ __nv_bfloat16 g_A1b[(size_t)CC * NCOL];
__device__ __nv_bfloat16 g_A1c[(size_t)CC * NCOL];
__device__ __nv_bfloat16 g_A2a[(size_t)CC * NCOL];
__device__ __nv_bfloat16 g_A2b[(size_t)CC * NCOL];
__device__ __nv_bfloat16 g_A2c[(size_t)CC * NCOL];
__device__ float g_A3[(size_t)CC * NCOL];            // layer3 out, fp32
__device__ __nv_bfloat16 g_W1a[CC*KP], g_W1b[CC*KP], g_W1c[CC*KP];
__device__ __nv_bfloat16 g_W2a[CC*CC], g_W2b[CC*CC], g_W2c[CC*CC];
__device__ __nv_bfloat16 g_W3a[CC*CC], g_W3b[CC*CC], g_W3c[CC*CC];
__device__ float g_Y [CC * NP];
__device__ float g_Y2[CC * NP];
__device__ float g_Y3[CC * NP];
__device__ float g_NET[OUTC * NP];
__device__ float g_NX[NP * 3];
__device__ int   g_IDX[NP * SS];

// ---------------- asm helpers (base-target only: sm_80+ instructions) ----------------
__device__ __forceinline__ uint32_t smem_u32(const void* p){
    uint32_t a;
    asm("{ .reg .u64 t; cvta.to.shared.u64 t, %1; cvt.u32.u64 %0, t; }" : "=r"(a) : "l"(p));
    return a;
}
#define CP16(dst, src)  asm volatile("cp.async.cg.shared.global [%0], [%1], 16;" :: "r"(dst), "l"(src))
#define CP_COMMIT()     asm volatile("cp.async.commit_group;" ::: "memory")
#define CP_WAIT1()      asm volatile("cp.async.wait_group 1;" ::: "memory")
#define CP_WAIT0()      asm volatile("cp.async.wait_group 0;" ::: "memory")

#define LDSM_X4(R, addr) \
    asm volatile("ldmatrix.sync.aligned.m8n8.x4.shared.b16 {%0,%1,%2,%3}, [%4];" \
        : "=r"((R)[0]),"=r"((R)[1]),"=r"((R)[2]),"=r"((R)[3]) : "r"(addr))
#define LDSM_X4T(R, addr) \
    asm volatile("ldmatrix.sync.aligned.m8n8.x4.trans.shared.b16 {%0,%1,%2,%3}, [%4];" \
        : "=r"((R)[0]),"=r"((R)[1]),"=r"((R)[2]),"=r"((R)[3]) : "r"(addr))

#define MMA_BF16(C, A, b0, b1) \
    asm volatile("mma.sync.aligned.m16n8k16.row.col.f32.bf16.bf16.f32 " \
        "{%0,%1,%2,%3}, {%4,%5,%6,%7}, {%8,%9}, {%0,%1,%2,%3};" \
        : "+f"((C)[0]),"+f"((C)[1]),"+f"((C)[2]),"+f"((C)[3]) \
        : "r"((A)[0]),"r"((A)[1]),"r"((A)[2]),"r"((A)[3]), "r"(b0),"r"(b1))

// ---------------- misc helpers ----------------
__device__ __forceinline__ float d2_nofma(float ax,float ay,float az,float bx,float by,float bz){
    float dx=ax-bx, dy=ay-by, dz=az-bz;
    return __fadd_rn(__fadd_rn(__fmul_rn(dx,dx),__fmul_rn(dy,dy)),__fmul_rn(dz,dz));
}
__device__ __forceinline__ void split3(float v, __nv_bfloat16& x1, __nv_bfloat16& x2, __nv_bfloat16& x3){
    x1 = __float2bfloat16(v);
    float r = v - __bfloat162float(x1);
    x2 = __float2bfloat16(r);
    float r2 = r - __bfloat162float(x2);
    x3 = __float2bfloat16(r2);
}

// ---------------- FPS: one block per batch ----------------
__global__ __launch_bounds__(1024) void fps_kernel(const float* __restrict__ xyz)
{
    __shared__ float sx[KK], sy[KK], sz[KK];
    __shared__ float rv[32]; __shared__ int ri[32]; __shared__ int sfar;
    const int b = blockIdx.x, tid = threadIdx.x;
    const float* xb = xyz + (size_t)b*KK*3;
    for (int i=tid;i<KK;i+=1024){ sx[i]=xb[i*3+0]; sy[i]=xb[i*3+1]; sz[i]=xb[i*3+2]; }
    __syncthreads();
    const int i0 = tid, i1 = tid + 1024;
    float d0 = 1e10f, d1 = 1e10f;
    int far = 0;
    const float x0=sx[i0], y0=sy[i0], z0=sz[i0];
    const float x1=sx[i1], y1=sy[i1], z1=sz[i1];
    for (int it=0; it<PP; ++it){
        if (tid==0){
            g_NX[(b*PP+it)*3+0]=sx[far];
            g_NX[(b*PP+it)*3+1]=sy[far];
            g_NX[(b*PP+it)*3+2]=sz[far];
        }
        const float cx=sx[far], cy=sy[far], cz=sz[far];
        d0 = fminf(d0, d2_nofma(x0,y0,z0,cx,cy,cz));
        d1 = fminf(d1, d2_nofma(x1,y1,z1,cx,cy,cz));
        float bv = d0; int bi = i0;
        if (d1 > bv){ bv=d1; bi=i1; }
        #pragma unroll
        for (int off=16; off; off>>=1){
            float ov=__shfl_down_sync(0xffffffffu,bv,off);
            int   oi=__shfl_down_sync(0xffffffffu,bi,off);
            if (ov>bv || (ov==bv && oi<bi)){ bv=ov; bi=oi; }
        }
        const int w = tid>>5, lane = tid&31;
        if (lane==0){ rv[w]=bv; ri[w]=bi; }
        __syncthreads();
        if (w==0){
            bv = rv[lane]; bi = ri[lane];
            #pragma unroll
            for (int off=16; off; off>>=1){
                float ov=__shfl_down_sync(0xffffffffu,bv,off);
                int   oi=__shfl_down_sync(0xffffffffu,bi,off);
                if (ov>bv || (ov==bv && oi<bi)){ bv=ov; bi=oi; }
            }
            if (lane==0) sfar = bi;
        }
        __syncthreads();
        far = sfar;
    }
}

// ---------------- ball query ----------------
__global__ __launch_bounds__(256) void ballq_kernel(const float* __restrict__ xyz)
{
    __shared__ float sx[KK], sy[KK], sz[KK];
    const int b = blockIdx.x >> 5;
    const float* xb = xyz + (size_t)b*KK*3;
    for (int i=threadIdx.x;i<KK;i+=256){ sx[i]=xb[i*3+0]; sy[i]=xb[i*3+1]; sz[i]=xb[i*3+2]; }
    __syncthreads();
    const int warp = threadIdx.x>>5, lane = threadIdx.x&31;
    const int w = blockIdx.x*8 + warp;
    const float cx=g_NX[w*3+0], cy=g_NX[w*3+1], cz=g_NX[w*3+2];
    int cnt=0, firstIdx=0; bool haveFirst=false;
    for (int j=0;j<KK;j+=32){
        const int i = j + lane;
        const float dd = d2_nofma(sx[i],sy[i],sz[i],cx,cy,cz);
        const bool within = dd < 0.09f;
        const unsigned mask = __ballot_sync(0xffffffffu, within);
        if (mask){
            if (!haveFirst){ firstIdx = j + __ffs(mask) - 1; haveFirst=true; }
            const int rank = __popc(mask & ((1u<<lane)-1u));
            if (within && (cnt+rank) < SS) g_IDX[w*SS + cnt + rank] = i;
            cnt += __popc(mask);
            if (cnt >= SS) break;
        }
    }
    if (cnt < SS && lane >= cnt && lane < SS) g_IDX[w*SS + lane] = firstIdx;
}

// ---------------- weight prep: fp32 -> 3 bf16 planes (with K pad) ----------------
__global__ void prep_split(const float* __restrict__ src,
                           __nv_bfloat16* __restrict__ da, __nv_bfloat16* __restrict__ db,
                           __nv_bfloat16* __restrict__ dc, int M, int Ksrc, int Kdst)
{
    int t = blockIdx.x*256 + threadIdx.x;
    if (t < M*Kdst){
        int m = t / Kdst, k = t % Kdst;
        float v = (k < Ksrc) ? src[m*Ksrc + k] : 0.0f;
        __nv_bfloat16 x1,x2,x3; split3(v,x1,x2,x3);
        da[t]=x1; db[t]=x2; dc[t]=x3;
    }
}

// ---------------- gather xyz channels into X1 rows 0..2 (3 planes) ----------------
__global__ void gatherx_kernel(const float* __restrict__ xyz)
{
    int t = blockIdx.x*256 + threadIdx.x;
    int b = t >> 12;
    int p = (t >> 4) & 255;
    int i = g_IDX[t];
    const float* xb = xyz + (size_t)b*KK*3 + (size_t)i*3;
    const float* nc = g_NX + (b*PP + p)*3;
    #pragma unroll
    for (int r=0;r<3;r++){
        float v = (xb[r]-nc[r]) / 0.3f;
        __nv_bfloat16 x1,x2,x3; split3(v,x1,x2,x3);
        g_X1a[(size_t)r*NCOL + t]=x1; g_X1b[(size_t)r*NCOL + t]=x2; g_X1c[(size_t)r*NCOL + t]=x3;
    }
}

// ---------------- gather features into X1 rows 3..258 (3 planes) ----------------
__global__ __launch_bounds__(256) void gatherf_kernel(const float* __restrict__ features)
{
    __shared__ float row[KK];
    const int c = blockIdx.x, b = blockIdx.y;
    const float* src = features + ((size_t)b*CC + c)*KK;
    for (int i=threadIdx.x;i<KK;i+=256) row[i]=src[i];
    __syncthreads();
    const size_t base = (size_t)(3+c)*NCOL + b*(PP*SS);
    const int* ib = g_IDX + b*(PP*SS);
    #pragma unroll
    for (int it=0; it<16; ++it){
        int cl = it*256 + threadIdx.x;
        float v = row[ib[cl]];
        __nv_bfloat16 x1,x2,x3; split3(v,x1,x2,x3);
        g_X1a[base+cl]=x1; g_X1b[base+cl]=x2; g_X1c[base+cl]=x3;
    }
}

// ---------------- mma.sync bf16 GEMM (3-plane split, 6 products) ----------------
// C[256][NCOL] = relu(BN(W @ X)); CTA tile 128x128, 8 warps of 64x32, BK=32.
#define A_PL 10240u            // 128 rows * 80B (32 bf16 + 8 pad)
#define A_BUFS (3u*A_PL)       // 30720
#define B_PL 8704u             // 32 rows * 272B (128 bf16 + 8 pad)
#define B_BUFS (3u*B_PL)       // 26112
#define BUFSZ (A_BUFS + B_BUFS)// 56832
#define SMT (2*BUFSZ)          // 113664

__global__ __launch_bounds__(256) void mma_gemm_kernel(
    const __nv_bfloat16* __restrict__ Aa, const __nv_bfloat16* __restrict__ Ab,
    const __nv_bfloat16* __restrict__ Ac, int Kw, int nch,
    const __nv_bfloat16* __restrict__ Ba, const __nv_bfloat16* __restrict__ Bb,
    const __nv_bfloat16* __restrict__ Bc,
    float* __restrict__ OutF,
    __nv_bfloat16* __restrict__ Oa, __nv_bfloat16* __restrict__ Ob, __nv_bfloat16* __restrict__ Oc,
    const float* __restrict__ gamma, const float* __restrict__ beta,
    const float* __restrict__ mean,  const float* __restrict__ var)
{
    extern __shared__ char smem[];
    const uint32_t sbase = smem_u32(smem);
    const int tid = threadIdx.x, lane = tid & 31, wid = tid >> 5;
    const int wm = wid & 1, wn = wid >> 1;
    const int n0 = blockIdx.x * 128;
    const int mbase = blockIdx.y * 128;

    // offset A to this CTA's row block
    const size_t aoff = (size_t)mbase * Kw;
    const __nv_bfloat16* A0 = Aa + aoff;
    const __nv_bfloat16* A1 = Ab + aoff;
    const __nv_bfloat16* A2 = Ac + aoff;

    auto stage = [&](int c, int buf){
        const int k0 = c * 32;
        const uint32_t sA = sbase + buf*BUFSZ;
        const uint32_t sB = sA + A_BUFS;
        #pragma unroll
        for (int it=0; it<2; ++it){
            const int idx = it*256 + tid;
            const int m = idx >> 2, kg = (idx & 3) * 8;
            const uint32_t d = sA + (uint32_t)m*80u + (uint32_t)kg*2u;
            const size_t so = (size_t)m*Kw + k0 + kg;
            CP16(d,          A0 + so);
            CP16(d + A_PL,   A1 + so);
            CP16(d + 2*A_PL, A2 + so);
        }
        #pragma unroll
        for (int it=0; it<2; ++it){
            const int idx = it*256 + tid;
            const int k = idx >> 4, ng = (idx & 15) * 8;
            const uint32_t d = sB + (uint32_t)k*272u + (uint32_t)ng*2u;
            const size_t so = (size_t)(k0+k)*NCOL + n0 + ng;
            CP16(d,          Ba + so);
            CP16(d + B_PL,   Bb + so);
            CP16(d + 2*B_PL, Bc + so);
        }
    };

    float acc[4][4][4] = {};

    const uint32_t aRow = (uint32_t)((wm*64 + (lane & 15)) * 80) + (uint32_t)(((lane >> 4) << 3) * 2);
    const uint32_t bRow = (uint32_t)(((((lane >> 3) & 1) << 3) + (lane & 7)) * 272)
                        + (uint32_t)((wn*32 + ((lane >> 4) << 3)) * 2);

    auto compute_chunk = [&](int buf){
        const uint32_t aB = sbase + buf*BUFSZ;
        const uint32_t bB = aB + A_BUFS;
        #pragma unroll
        for (int ks=0; ks<2; ++ks){
            uint32_t bfr[3][2][4];
            #pragma unroll
            for (int p=0; p<3; ++p)
                #pragma unroll
                for (int n2=0; n2<2; ++n2)
                    LDSM_X4T(bfr[p][n2], bB + p*B_PL + bRow + (uint32_t)(ks*16*272) + (uint32_t)(n2*32));
            #pragma unroll
            for (int mh=0; mh<2; ++mh){
                uint32_t afr[3][2][4];
                #pragma unroll
                for (int p=0; p<3; ++p)
                    #pragma unroll
                    for (int m2=0; m2<2; ++m2)
                        LDSM_X4(afr[p][m2], aB + p*A_PL + aRow + (uint32_t)((mh*2+m2)*16*80) + (uint32_t)(ks*32));
                #pragma unroll
                for (int m2=0; m2<2; ++m2){
                    const int mi = mh*2 + m2;
                    #pragma unroll
                    for (int ni=0; ni<4; ++ni){
                        const int n2 = ni >> 1, q = (ni & 1) * 2;
                        float* C = acc[mi][ni];
                        MMA_BF16(C, afr[0][m2], bfr[0][n2][q], bfr[0][n2][q+1]); // 1*1
                        MMA_BF16(C, afr[0][m2], bfr[1][n2][q], bfr[1][n2][q+1]); // 1*2
                        MMA_BF16(C, afr[1][m2], bfr[0][n2][q], bfr[0][n2][q+1]); // 2*1
                        MMA_BF16(C, afr[0][m2], bfr[2][n2][q], bfr[2][n2][q+1]); // 1*3
                        MMA_BF16(C, afr[2][m2], bfr[0][n2][q], bfr[0][n2][q+1]); // 3*1
                        MMA_BF16(C, afr[1][m2], bfr[1][n2][q], bfr[1][n2][q+1]); // 2*2
                    }
                }
            }
        }
    };

    stage(0, 0);
    CP_COMMIT();
    for (int c=0; c<nch; ++c){
        if (c+1 < nch){ stage(c+1, (c+1)&1); CP_COMMIT(); CP_WAIT1(); }
        else          { CP_WAIT0(); }
        __syncthreads();
        compute_chunk(c & 1);
        __syncthreads();
    }

    // ---- epilogue: BN + ReLU, then fp32 or 3-plane bf16 output ----
    #pragma unroll
    for (int mi=0; mi<4; ++mi){
        const int mlo = mbase + wm*64 + mi*16 + (lane >> 2);
        const int mhi = mlo + 8;
        const float s0 = gamma[mlo] * rsqrtf(var[mlo] + 1e-5f);
        const float h0 = beta[mlo] - mean[mlo]*s0;
        const float s1 = gamma[mhi] * rsqrtf(var[mhi] + 1e-5f);
        const float h1 = beta[mhi] - mean[mhi]*s1;
        #pragma unroll
        for (int ni=0; ni<4; ++ni){
            const int n = n0 + wn*32 + ni*8 + (lane & 3)*2;
            const float v0 = fmaxf(acc[mi][ni][0]*s0 + h0, 0.f);
            const float v1 = fmaxf(acc[mi][ni][1]*s0 + h0, 0.f);
            const float v2 = fmaxf(acc[mi][ni][2]*s1 + h1, 0.f);
            const float v3 = fmaxf(acc[mi][ni][3]*s1 + h1, 0.f);
            if (OutF){
                *reinterpret_cast<float2*>(&OutF[(size_t)mlo*NCOL + n]) = make_float2(v0, v1);
                *reinterpret_cast<float2*>(&OutF[(size_t)mhi*NCOL + n]) = make_float2(v2, v3);
            } else {
                __nv_bfloat16 a0,b0p,c0p, a1,b1p,c1p, a2,b2p,c2p, a3,b3p,c3p;
                split3(v0,a0,b0p,c0p); split3(v1,a1,b1p,c1p);
                split3(v2,a2,b2p,c2p); split3(v3,a3,b3p,c3p);
                const size_t ilo = (size_t)mlo*NCOL + n, ihi = (size_t)mhi*NCOL + n;
                __nv_bfloat162 t;
                t.x=a0;  t.y=a1;  *reinterpret_cast<__nv_bfloat162*>(&Oa[ilo]) = t;
                t.x=b0p; t.y=b1p; *reinterpret_cast<__nv_bfloat162*>(&Ob[ilo]) = t;
                t.x=c0p; t.y=c1p; *reinterpret_cast<__nv_bfloat162*>(&Oc[ilo]) = t;
                t.x=a2;  t.y=a3;  *reinterpret_cast<__nv_bfloat162*>(&Oa[ihi]) = t;
                t.x=b2p; t.y=b3p; *reinterpret_cast<__nv_bfloat162*>(&Ob[ihi]) = t;
                t.x=c2p; t.y=c3p; *reinterpret_cast<__nv_bfloat162*>(&Oc[ihi]) = t;
            }
        }
    }
}

// ---------------- SIMT GEMM (proposal FCs) ----------------
#define BMt 64
#define BNt 64
#define BKt 16
__global__ __launch_bounds__(256) void gemm_kernel(
    const float* __restrict__ W, const float* __restrict__ X, float* __restrict__ Out,
    int M, int Kc, int N,
    const float* __restrict__ gamma, const float* __restrict__ beta,
    const float* __restrict__ mean,  const float* __restrict__ var,
    const float* __restrict__ bias, int do_relu)
{
    __shared__ float Ws[BKt][BMt+4];
    __shared__ float Xs[BKt][BNt+4];
    const int tid = threadIdx.x;
    const int tx = tid & 15, ty = tid >> 4;
    const int row0 = blockIdx.y*BMt, col0 = blockIdx.x*BNt;
    float acc[4][4] = {};
    const int wm = tid >> 2;
    const int wk = (tid & 3) * 4;
    const int xk = tid >> 4;
    const int xn = (tid & 15) * 4;

    for (int kt=0; kt<Kc; kt+=BKt){
        float4 wv = make_float4(0.f,0.f,0.f,0.f);
        const int gm = row0 + wm;
        if (gm < M) wv = *reinterpret_cast<const float4*>(&W[(size_t)gm*Kc + kt + wk]);
        Ws[wk+0][wm]=wv.x; Ws[wk+1][wm]=wv.y; Ws[wk+2][wm]=wv.z; Ws[wk+3][wm]=wv.w;
        float4 xv = *reinterpret_cast<const float4*>(&X[(size_t)(kt+xk)*N + col0 + xn]);
        *reinterpret_cast<float4*>(&Xs[xk][xn]) = xv;
        __syncthreads();
        #pragma unroll
        for (int k=0;k<BKt;k++){
            float a0=Ws[k][ty*4+0], a1=Ws[k][ty*4+1], a2=Ws[k][ty*4+2], a3=Ws[k][ty*4+3];
            float b0=Xs[k][tx*4+0], b1=Xs[k][tx*4+1], b2=Xs[k][tx*4+2], b3=Xs[k][tx*4+3];
            acc[0][0]+=a0*b0; acc[0][1]+=a0*b1; acc[0][2]+=a0*b2; acc[0][3]+=a0*b3;
            acc[1][0]+=a1*b0; acc[1][1]+=a1*b1; acc[1][2]+=a1*b2; acc[1][3]+=a1*b3;
            acc[2][0]+=a2*b0; acc[2][1]+=a2*b1; acc[2][2]+=a2*b2; acc[2][3]+=a2*b3;
            acc[3][0]+=a3*b0; acc[3][1]+=a3*b1; acc[3][2]+=a3*b2; acc[3][3]+=a3*b3;
        }
        __syncthreads();
    }
    #pragma unroll
    for (int i=0;i<4;i++){
        const int m = row0 + ty*4 + i;
        if (m >= M) continue;
        float s = 1.f, sh = 0.f;
        if (gamma){
            const float sc = gamma[m] * rsqrtf(var[m] + 1e-5f);
            s = sc; sh = beta[m] - mean[m]*sc;
        } else if (bias){
            sh = bias[m];
        }
        float4 o;
        o.x = acc[i][0]*s + sh; o.y = acc[i][1]*s + sh;
        o.z = acc[i][2]*s + sh; o.w = acc[i][3]*s + sh;
        if (do_relu){
            o.x=fmaxf(o.x,0.f); o.y=fmaxf(o.y,0.f); o.z=fmaxf(o.z,0.f); o.w=fmaxf(o.w,0.f);
        }
        *reinterpret_cast<float4*>(&Out[(size_t)m*N + col0 + tx*4]) = o;
    }
}

// ---------------- max over samples ----------------
__global__ void maxpool_kernel()
{
    int id = blockIdx.x*256 + threadIdx.x;
    int oc = id >> 13, cp = id & (NP-1);
    const float4* p = reinterpret_cast<const float4*>(g_A3 + (size_t)oc*NCOL + cp*SS);
    float4 a=p[0], b=p[1], c=p[2], d=p[3];
    float m = fmaxf(fmaxf(fmaxf(a.x,a.y),fmaxf(a.z,a.w)),
               fmaxf(fmaxf(fmaxf(b.x,b.y),fmaxf(b.z,b.w)),
               fmaxf(fmaxf(fmaxf(c.x,c.y),fmaxf(c.z,c.w)),
                     fmaxf(fmaxf(d.x,d.y),fmaxf(d.z,d.w)))));
    g_Y[(size_t)oc*NP + cp] = m;
}

// ---------------- head ----------------
__global__ __launch_bounds__(256) void head_kernel(const float* __restrict__ msa,
                                                   float* __restrict__ out)
{
    const int t = blockIdx.x*256 + threadIdx.x;
    #define NT(j) g_NET[(j)*NP + t]
    const float obj0 = NT(0), obj1 = NT(1);
    out[OFF_OBJ + t*2 + 0] = obj0;
    out[OFF_OBJ + t*2 + 1] = obj1;
    const float c0 = g_NX[t*3+0] + NT(2);
    const float c1 = g_NX[t*3+1] + NT(3);
    const float c2 = g_NX[t*3+2] + NT(4);
    out[OFF_CENTER + t*3 + 0] = c0;
    out[OFF_CENTER + t*3 + 1] = c1;
    out[OFF_CENTER + t*3 + 2] = c2;

    float ss[18];
    #pragma unroll
    for (int k=0;k<18;k++){ ss[k] = NT(29+k); out[OFF_SS + t*18 + k] = ss[k]; }
    int best = 0; float bv = ss[0];
    #pragma unroll
    for (int k=1;k<18;k++) if (ss[k] > bv){ bv = ss[k]; best = k; }

    float ps0=0.f, ps1=0.f, ps2=0.f;
    #pragma unroll
    for (int k=0;k<18;k++){
        const float m0=msa[k*3+0], m1=msa[k*3+1], m2=msa[k*3+2];
        const float r0 = NT(47+k*3+0)*m0;
        const float r1 = NT(47+k*3+1)*m1;
        const float r2 = NT(47+k*3+2)*m2;
        out[OFF_SRES + t*54 + k*3 + 0] = r0;
        out[OFF_SRES + t*54 + k*3 + 1] = r1;
        out[OFF_SRES + t*54 + k*3 + 2] = r2;
        if (k == best){ ps0 = r0+m0; ps1 = r1+m1; ps2 = r2+m2; }
    }
    out[OFF_PSIZE + t*3 + 0] = ps0;
    out[OFF_PSIZE + t*3 + 1] = ps1;
    out[OFF_PSIZE + t*3 + 2] = ps2;

    float sm[18];
    #pragma unroll
    for (int k=0;k<18;k++){ sm[k] = NT(101+k); out[OFF_SEM + t*18 + k] = sm[k]; }

    const float cc0 = c0, cc1 = c2, cc2 = -c1;
    const float hx = ps0*0.5f, hy = ps2*0.5f, hz = ps1*0.5f;
    const float SX[8]={1,1,-1,-1,1,1,-1,-1};
    const float SY[8]={1,1,1,1,-1,-1,-1,-1};
    const float SZ[8]={1,-1,-1,1,1,-1,-1,1};
    #pragma unroll
    for (int i=0;i<8;i++){
        out[OFF_CORN + t*24 + i*3 + 0] = cc0 + hx*SX[i];
        out[OFF_CORN + t*24 + i*3 + 1] = cc1 + hy*SY[i];
        out[OFF_CORN + t*24 + i*3 + 2] = cc2 + hz*SZ[i];
    }

    #pragma unroll
    for (int k=0;k<18;k++) out[OFF_SLOG + t*19 + k] = sm[k];
    out[OFF_SLOG + t*19 + 18] = (obj0 <= obj1) ? 0.0f : 1e10f;

    {
        const float mx = fmaxf(obj0,obj1);
        const float e0 = expf(obj0-mx), e1 = expf(obj1-mx);
        out[OFF_OPROB + t] = e1/(e0+e1);
    }
    {
        float mx = sm[0];
        #pragma unroll
        for (int k=1;k<18;k++) mx = fmaxf(mx, sm[k]);
        float e[18], ssum = 0.f;
        #pragma unroll
        for (int k=0;k<18;k++){ e[k] = expf(sm[k]-mx); ssum += e[k]; }
        #pragma unroll
        for (int k=0;k<18;k++) out[OFF_SPROB + t*18 + k] = e[k]/ssum;
    }
    #undef NT
}

// ---------------- host launcher ----------------
extern "C" void kernel_launch(void* const* d_in, const int* in_sizes, int n_in,
                              void* d_out, int out_size)
{
    const float* xyz      = (const float*)d_in[0];
    const float* features = (const float*)d_in[1];
    const float* sa_w1    = (const float*)d_in[2];
    const float* sa_w2    = (const float*)d_in[3];
    const float* sa_w3    = (const float*)d_in[4];
    const float* sa_gamma = (const float*)d_in[5];
    const float* sa_beta  = (const float*)d_in[6];
    const float* sa_mean  = (const float*)d_in[7];
    const float* sa_var   = (const float*)d_in[8];
    const float* p_w1     = (const float*)d_in[9];
    const float* p_w2     = (const float*)d_in[10];
    const float* p_w3     = (const float*)d_in[11];
    const float* p_b3     = (const float*)d_in[12];
    const float* p_gamma  = (const float*)d_in[13];
    const float* p_beta   = (const float*)d_in[14];
    const float* p_mean   = (const float*)d_in[15];
    const float* p_var    = (const float*)d_in[16];
    const float* msa      = (const float*)d_in[17];
    float* out = (float*)d_out;

    cudaFuncSetAttribute(mma_gemm_kernel, cudaFuncAttributeMaxDynamicSharedMemorySize, SMT);

    void *pX1a,*pX1b,*pX1c, *pA1a,*pA1b,*pA1c, *pA2a,*pA2b,*pA2c;
    void *pW1a,*pW1b,*pW1c, *pW2a,*pW2b,*pW2c, *pW3a,*pW3b,*pW3c;
    void *pA3, *pY, *pY2, *pY3, *pNET;
    cudaGetSymbolAddress(&pX1a, g_X1a); cudaGetSymbolAddress(&pX1b, g_X1b); cudaGetSymbolAddress(&pX1c, g_X1c);
    cudaGetSymbolAddress(&pA1a, g_A1a); cudaGetSymbolAddress(&pA1b, g_A1b); cudaGetSymbolAddress(&pA1c, g_A1c);
    cudaGetSymbolAddress(&pA2a, g_A2a); cudaGetSymbolAddress(&pA2b, g_A2b); cudaGetSymbolAddress(&pA2c, g_A2c);
    cudaGetSymbolAddress(&pW1a, g_W1a); cudaGetSymbolAddress(&pW1b, g_W1b); cudaGetSymbolAddress(&pW1c, g_W1c);
    cudaGetSymbolAddress(&pW2a, g_W2a); cudaGetSymbolAddress(&pW2b, g_W2b); cudaGetSymbolAddress(&pW2c, g_W2c);
    cudaGetSymbolAddress(&pW3a, g_W3a); cudaGetSymbolAddress(&pW3b, g_W3b); cudaGetSymbolAddress(&pW3c, g_W3c);
    cudaGetSymbolAddress(&pA3, g_A3);
    cudaGetSymbolAddress(&pY,  g_Y);
    cudaGetSymbolAddress(&pY2, g_Y2);
    cudaGetSymbolAddress(&pY3, g_Y3);
    cudaGetSymbolAddress(&pNET, g_NET);

    fps_kernel<<<BB, 1024>>>(xyz);
    ballq_kernel<<<1024, 256>>>(xyz);
    prep_split<<<(CC*KP + 255)/256, 256>>>(sa_w1, (__nv_bfloat16*)pW1a, (__nv_bfloat16*)pW1b, (__nv_bfloat16*)pW1c, CC, 259, KP);
    prep_split<<<(CC*CC + 255)/256, 256>>>(sa_w2, (__nv_bfloat16*)pW2a, (__nv_bfloat16*)pW2b, (__nv_bfloat16*)pW2c, CC, CC, CC);
    prep_split<<<(CC*CC + 255)/256, 256>>>(sa_w3, (__nv_bfloat16*)pW3a, (__nv_bfloat16*)pW3b, (__nv_bfloat16*)pW3c, CC, CC, CC);
    gatherx_kernel<<<NCOL/256, 256>>>(xyz);
    gatherf_kernel<<<dim3(CC, BB), 256>>>(features);

    const dim3 gg(NCOL/128, 2);
    // layer 1: K=320 (10 chunks)
    mma_gemm_kernel<<<gg, 256, SMT>>>(
        (const __nv_bfloat16*)pW1a, (const __nv_bfloat16*)pW1b, (const __nv_bfloat16*)pW1c, KP, KP/32,
        (const __nv_bfloat16*)pX1a, (const __nv_bfloat16*)pX1b, (const __nv_bfloat16*)pX1c,
        nullptr, (__nv_bfloat16*)pA1a, (__nv_bfloat16*)pA1b, (__nv_bfloat16*)pA1c,
        sa_gamma+0, sa_beta+0, sa_mean+0, sa_var+0);
    // layer 2
    mma_gemm_kernel<<<gg, 256, SMT>>>(
        (const __nv_bfloat16*)pW2a, (const __nv_bfloat16*)pW2b, (const __nv_bfloat16*)pW2c, CC, CC/32,
        (const __nv_bfloat16*)pA1a, (const __nv_bfloat16*)pA1b, (const __nv_bfloat16*)pA1c,
        nullptr, (__nv_bfloat16*)pA2a, (__nv_bfloat16*)pA2b, (__nv_bfloat16*)pA2c,
        sa_gamma+256, sa_beta+256, sa_mean+256, sa_var+256);
    // layer 3 -> fp32
    mma_gemm_kernel<<<gg, 256, SMT>>>(
        (const __nv_bfloat16*)pW3a, (const __nv_bfloat16*)pW3b, (const __nv_bfloat16*)pW3c, CC, CC/32,
        (const __nv_bfloat16*)pA2a, (const __nv_bfloat16*)pA2b, (const __nv_bfloat16*)pA2c,
        (float*)pA3, nullptr, nullptr, nullptr,
        sa_gamma+512, sa_beta+512, sa_mean+512, sa_var+512);

    maxpool_kernel<<<(CC*NP)/256, 256>>>();

    gemm_kernel<<<dim3(NP/BNt, CC/BMt), 256>>>(p_w1, (const float*)pY, (float*)pY2,
        CC, CC, NP, p_gamma+0, p_beta+0, p_mean+0, p_var+0, nullptr, 1);
    gemm_kernel<<<dim3(NP/BNt, CC/BMt), 256>>>(p_w2, (const float*)pY2, (float*)pY3,
        CC, CC, NP, p_gamma+256, p_beta+256, p_mean+256, p_var+256, nullptr, 1);
    gemm_kernel<<<dim3(NP/BNt, (OUTC+BMt-1)/BMt), 256>>>(p_w3, (const float*)pY3, (float*)pNET,
        OUTC, CC, NP, nullptr, nullptr, nullptr, nullptr, p_b3, 0);

    head_kernel<<<NP/256, 256>>>(msa, out);
}